// round 1
// baseline (speedup 1.0000x reference)
#include <cuda_runtime.h>
#include <math.h>

// GenomicLogicBraidIntegrator: Gauss linking integral between
//   r1 = normalized quaternion curve from starcoder_bytes (4096 pts)
//   r2 = last-3 components of normalize(eye(4)[hg38_indices])  (4096 pts)
//
// KEY IDENTITY: r2[j] takes only 4 distinct values, so (dr2[j], m2[j]) is
// determined by the pair (idx[j], idx[j+1]) -> at most 16 distinct segment
// descriptors. The O(N^2) double sum collapses EXACTLY to
//   sum_i sum_{g<16} count[g] * term(i, g)
// i.e. 4095*16 terms instead of 4095*4095.

#define NPTS 4096
#define NSEG 4095
#define EPSF 1e-9f
#define NBLK 32
#define NTHR 128

__device__ float  g_cnt[16];
__device__ float  g_dr2[16][3];
__device__ float  g_m2[16][3];
__device__ double g_partial[NBLK];

// ---------------------------------------------------------------------------
// Kernel 1: histogram of (idx[j], idx[j+1]) pairs + the 16 (dr2, m2) consts
// ---------------------------------------------------------------------------
__global__ void prep_kernel(const int* __restrict__ idx, int n)
{
    __shared__ int hist[16];
    int tid = threadIdx.x;
    if (tid < 16) hist[tid] = 0;
    __syncthreads();

    for (int j = tid; j < n - 1; j += blockDim.x) {
        int a = idx[j];
        int b = idx[j + 1];
        atomicAdd(&hist[(a << 2) | b], 1);
    }
    __syncthreads();

    if (tid < 16) {
        int a = tid >> 2;
        int b = tid & 3;
        // normalize(e_v) = e_v / sqrt(1 + EPS); take components 1..3
        float s = 1.0f / sqrtf(1.0f + EPSF);
        float ra[3] = {0.f, 0.f, 0.f};
        float rb[3] = {0.f, 0.f, 0.f};
        if (a > 0) ra[a - 1] = s;
        if (b > 0) rb[b - 1] = s;
        #pragma unroll
        for (int k = 0; k < 3; k++) {
            g_dr2[tid][k] = rb[k] - ra[k];
            g_m2 [tid][k] = 0.5f * (rb[k] + ra[k]);
        }
        g_cnt[tid] = (float)hist[tid];
    }
}

// ---------------------------------------------------------------------------
// Kernel 2: per-i contribution over the 16 groups, block-reduced partials
// ---------------------------------------------------------------------------
__global__ void __launch_bounds__(NTHR)
braid_kernel(const float* __restrict__ bytes)
{
    const int i = blockIdx.x * NTHR + threadIdx.x;

    double acc = 0.0;
    if (i < NSEG) {
        const float TWO_PI = 6.283185307179586476925f;

        float t0 = (bytes[i]     / 255.0f) * TWO_PI;
        float t1 = (bytes[i + 1] / 255.0f) * TWO_PI;
        float s0, c0, s1, c1;
        sincosf(t0, &s0, &c0);
        sincosf(t1, &s1, &c1);

        // quaternion [c, 0.5s, 0.3s, 0.2s], normalized; keep last 3 comps
        float x0 = 0.5f * s0, y0 = 0.3f * s0, z0 = 0.2f * s0;
        float x1 = 0.5f * s1, y1 = 0.3f * s1, z1 = 0.2f * s1;
        float inv0 = rsqrtf(c0 * c0 + x0 * x0 + y0 * y0 + z0 * z0 + EPSF);
        float inv1 = rsqrtf(c1 * c1 + x1 * x1 + y1 * y1 + z1 * z1 + EPSF);
        x0 *= inv0; y0 *= inv0; z0 *= inv0;
        x1 *= inv1; y1 *= inv1; z1 *= inv1;

        // segment i of curve 1
        float dx1 = x1 - x0, dy1 = y1 - y0, dz1 = z1 - z0;
        float mx1 = 0.5f * (x1 + x0), my1 = 0.5f * (y1 + y0), mz1 = 0.5f * (z1 + z0);

        #pragma unroll
        for (int g = 0; g < 16; g++) {
            float cnt = g_cnt[g];
            float ax = g_dr2[g][0], ay = g_dr2[g][1], az = g_dr2[g][2];
            // cross(dr1, dr2_g)
            float cx = dy1 * az - dz1 * ay;
            float cy = dz1 * ax - dx1 * az;
            float cz = dx1 * ay - dy1 * ax;
            // diff = m1 - m2_g
            float fx = mx1 - g_m2[g][0];
            float fy = my1 - g_m2[g][1];
            float fz = mz1 - g_m2[g][2];
            float num = cx * fx + cy * fy + cz * fz;
            float d2  = fx * fx + fy * fy + fz * fz + EPSF;
            float rin = rsqrtf(d2);                 // d2^-1.5 = rin^3
            float term = num * (rin * rin * rin);
            acc += (double)(cnt * term);
        }
    }

    // block tree-reduction in shared memory (deterministic order)
    __shared__ double sm[NTHR];
    sm[threadIdx.x] = acc;
    __syncthreads();
    #pragma unroll
    for (int off = NTHR / 2; off > 0; off >>= 1) {
        if (threadIdx.x < off) sm[threadIdx.x] += sm[threadIdx.x + off];
        __syncthreads();
    }
    if (threadIdx.x == 0) g_partial[blockIdx.x] = sm[0];
}

// ---------------------------------------------------------------------------
// Kernel 3: fold partials, scale by 1/(4*pi), emit fp32 scalar
// ---------------------------------------------------------------------------
__global__ void final_kernel(float* __restrict__ out)
{
    int lane = threadIdx.x;
    double v = (lane < NBLK) ? g_partial[lane] : 0.0;
    #pragma unroll
    for (int off = 16; off > 0; off >>= 1)
        v += __shfl_down_sync(0xffffffffu, v, off);
    if (lane == 0)
        out[0] = (float)(v / (4.0 * 3.14159265358979323846));
}

// ---------------------------------------------------------------------------
extern "C" void kernel_launch(void* const* d_in, const int* in_sizes, int n_in,
                              void* d_out, int out_size)
{
    const float* bytes = (const float*)d_in[0];   // starcoder_bytes, 4096 f32
    const int*   idx   = (const int*)d_in[1];     // hg38_indices,   4096 i32
    float*       out   = (float*)d_out;

    int n = in_sizes[0];   // 4096

    prep_kernel<<<1, 256>>>(idx, n);
    braid_kernel<<<NBLK, NTHR>>>(bytes);
    final_kernel<<<1, 32>>>(out);
}

// round 3
// speedup vs baseline: 1.2544x; 1.2544x over previous
#include <cuda_runtime.h>
#include <math.h>

// GenomicLogicBraidIntegrator — fully fused single-launch version.
//
// r2[j] takes only 4 distinct values, so (dr2[j], m2[j]) is determined by
// (idx[j], idx[j+1]) -> 16 distinct segment descriptors. The O(N^2) Gauss
// linking sum collapses EXACTLY to sum_i sum_{g<16} count[g] * term(i,g).
//
// Single kernel: each block redundantly builds the 16-bin histogram (cheap,
// L2-resident), computes its slice of i-terms, block-reduces in double, and
// the last block (fenced ticket) folds the 32 partials in fixed order.

#define EPSF 1e-9f
#define NBLK 32
#define NTHR 128

__device__ double       g_partial[NBLK];
__device__ unsigned int g_ticket = 0;

__global__ void __launch_bounds__(NTHR)
braid_fused_kernel(const float* __restrict__ bytes,
                   const int*   __restrict__ idx,
                   int n, float* __restrict__ out)
{
    const int tid  = threadIdx.x;
    const int nseg = n - 1;

    // ---- Phase 1: per-block 16-bin histogram + group constants ----------
    __shared__ int   hist[16];
    __shared__ float s_cnt[16];
    __shared__ float s_dr2[16][3];
    __shared__ float s_m2 [16][3];

    if (tid < 16) hist[tid] = 0;
    __syncthreads();

    for (int j = tid; j < nseg; j += NTHR) {
        int a = idx[j];
        int b = idx[j + 1];
        atomicAdd(&hist[(a << 2) | b], 1);
    }
    __syncthreads();

    if (tid < 16) {
        int a = tid >> 2;
        int b = tid & 3;
        float s = 1.0f / sqrtf(1.0f + EPSF);   // normalize(e_v) component
        float ra[3] = {0.f, 0.f, 0.f};
        float rb[3] = {0.f, 0.f, 0.f};
        if (a > 0) ra[a - 1] = s;
        if (b > 0) rb[b - 1] = s;
        #pragma unroll
        for (int k = 0; k < 3; k++) {
            s_dr2[tid][k] = rb[k] - ra[k];
            s_m2 [tid][k] = 0.5f * (rb[k] + ra[k]);
        }
        s_cnt[tid] = (float)hist[tid];
    }
    __syncthreads();

    // ---- Phase 2: per-i contribution over the 16 groups ------------------
    double acc = 0.0;
    const int i = blockIdx.x * NTHR + tid;
    if (i < nseg) {
        const float TWO_PI = 6.283185307179586476925f;

        float t0 = (bytes[i]     / 255.0f) * TWO_PI;
        float t1 = (bytes[i + 1] / 255.0f) * TWO_PI;
        float s0, c0, s1, c1;
        sincosf(t0, &s0, &c0);
        sincosf(t1, &s1, &c1);

        float x0 = 0.5f * s0, y0 = 0.3f * s0, z0 = 0.2f * s0;
        float x1 = 0.5f * s1, y1 = 0.3f * s1, z1 = 0.2f * s1;
        float inv0 = rsqrtf(c0 * c0 + x0 * x0 + y0 * y0 + z0 * z0 + EPSF);
        float inv1 = rsqrtf(c1 * c1 + x1 * x1 + y1 * y1 + z1 * z1 + EPSF);
        x0 *= inv0; y0 *= inv0; z0 *= inv0;
        x1 *= inv1; y1 *= inv1; z1 *= inv1;

        float dx1 = x1 - x0, dy1 = y1 - y0, dz1 = z1 - z0;
        float mx1 = 0.5f * (x1 + x0), my1 = 0.5f * (y1 + y0), mz1 = 0.5f * (z1 + z0);

        #pragma unroll
        for (int g = 0; g < 16; g++) {
            float cnt = s_cnt[g];
            float ax = s_dr2[g][0], ay = s_dr2[g][1], az = s_dr2[g][2];
            float cx = dy1 * az - dz1 * ay;
            float cy = dz1 * ax - dx1 * az;
            float cz = dx1 * ay - dy1 * ax;
            float fx = mx1 - s_m2[g][0];
            float fy = my1 - s_m2[g][1];
            float fz = mz1 - s_m2[g][2];
            float num = cx * fx + cy * fy + cz * fz;
            float d2  = fx * fx + fy * fy + fz * fz + EPSF;
            float rin = rsqrtf(d2);                  // d2^-1.5 = rin^3
            acc += (double)(cnt * (num * (rin * rin * rin)));
        }
    }

    // ---- Phase 3: deterministic block reduction -------------------------
    __shared__ double sm[NTHR];
    sm[tid] = acc;
    __syncthreads();
    #pragma unroll
    for (int off = NTHR / 2; off > 0; off >>= 1) {
        if (tid < off) sm[tid] += sm[tid + off];
        __syncthreads();
    }

    __shared__ bool amLast;
    if (tid == 0) {
        g_partial[blockIdx.x] = sm[0];
        __threadfence();
        unsigned int t = atomicInc(&g_ticket, NBLK - 1);  // wraps to 0 at NBLK-1
        amLast = (t == NBLK - 1);
    }
    __syncthreads();

    // ---- Phase 4: last block folds partials in fixed order --------------
    if (amLast && tid < 32) {
        double v = g_partial[tid];        // NBLK == 32 lanes
        #pragma unroll
        for (int off = 16; off > 0; off >>= 1)
            v += __shfl_down_sync(0xffffffffu, v, off);
        if (tid == 0)
            out[0] = (float)(v / (4.0 * 3.14159265358979323846));
    }
}

extern "C" void kernel_launch(void* const* d_in, const int* in_sizes, int n_in,
                              void* d_out, int out_size)
{
    const float* bytes = (const float*)d_in[0];   // starcoder_bytes, 4096 f32
    const int*   idx   = (const int*)d_in[1];     // hg38_indices,   4096 i32
    float*       out   = (float*)d_out;

    int n = in_sizes[0];   // 4096

    braid_fused_kernel<<<NBLK, NTHR>>>(bytes, idx, n, out);
}